// round 5
// baseline (speedup 1.0000x reference)
#include <cuda_runtime.h>
#include <cuda_bf16.h>
#include <math.h>

// FrameAlignment: B=16, S=2048, F=64
//   dist[b,i,j] = |score[b,i] - t[j]|
//   path = softmax_j(-dist)           (max-shift is softmax-invariant)
//   aligned = path @ feature
//
// Separable trick: exp(-|s-t|) = min(e^t * e^-s, e^-t * e^s).
// With t sorted ascending and k_i = #{t_j <= s_i}:
//   num[f] = e^-s * PrefEF[k][f] + e^s * SufENF[k][f]
//   W      = e^-s * prefE[k]      + e^s * sufEN[k]
//   aligned = num / W ;  path[i][j] = min(E_j*e^-s, EN_j*e^s) / W

#define B 16
#define S 2048
#define F 64

// ---------------- scratch (__device__ globals; no allocation allowed) -------
__device__ float  g_tsort[S];
__device__ int    g_perm[S];
__device__ float2 g_EEN[S];        // original order: (exp(t_j), exp(-t_j))
__device__ float  g_Esort[S];
__device__ float  g_ENsort[S];
__device__ float  g_prefE[S + 1];  // exclusive prefix of Esort
__device__ float  g_sufEN[S + 1];  // suffix of ENsort
__device__ float4 g_rowc[B * S];   // per row: (es, ens, 1/W, bitcast(k))
__device__ float  g_PrefEF[B * (S + 1) * F];  // 8.39 MB
__device__ float  g_SufENF[B * (S + 1) * F];  // 8.39 MB

// ---------------- K1: sort template, exp tables, scalar fp64 scans ----------
__global__ void k1_setup(const float* __restrict__ tmpl) {
    __shared__ double sdA[S];   // 16KB, aliased as float for sort values
    __shared__ double sdB[S];   // 16KB, aliased as int for sort indices
    float* sv = (float*)sdA;
    int*   si = (int*)sdB;
    int tid = threadIdx.x;      // 1024 threads

    for (int i = tid; i < S; i += 1024) {
        float tv = tmpl[i];
        sv[i] = tv; si[i] = i;
        g_EEN[i] = make_float2(expf(tv), expf(-tv));
    }
    __syncthreads();

    // bitonic sort ascending (value + index payload), n=2048, 1024 pairs/step
    for (int ksz = 2; ksz <= S; ksz <<= 1) {
        for (int jj = ksz >> 1; jj > 0; jj >>= 1) {
            int i   = ((tid / jj) * jj * 2) + (tid % jj);
            int ixj = i + jj;
            bool up = ((i & ksz) == 0);
            float a = sv[i], b = sv[ixj];
            if ((a > b) == up) {
                sv[i] = b; sv[ixj] = a;
                int pa = si[i]; si[i] = si[ixj]; si[ixj] = pa;
            }
            __syncthreads();
        }
    }

    // flush sorted results; keep exps in registers for the scans
    float ev[2], env[2];
    for (int c = 0; c < 2; c++) {
        int i = tid + 1024 * c;
        float v = sv[i];
        g_tsort[i] = v; g_perm[i] = si[i];
        float e  = expf(v);
        float en = expf(-v);
        g_Esort[i] = e; g_ENsort[i] = en;
        ev[c] = e; env[c] = en;
    }
    __syncthreads();

    // --- scan 1: inclusive fp64 prefix of Esort -> exclusive g_prefE
    for (int c = 0; c < 2; c++) sdA[tid + 1024 * c] = (double)ev[c];
    double* a = sdA; double* b2 = sdB;
    for (int off = 1; off < S; off <<= 1) {
        __syncthreads();
        for (int c = 0; c < 2; c++) {
            int i = tid + 1024 * c;
            double v = a[i];
            if (i >= off) v += a[i - off];
            b2[i] = v;
        }
        double* t = a; a = b2; b2 = t;
    }
    __syncthreads();
    for (int c = 0; c < 2; c++) {
        int i = tid + 1024 * c;
        g_prefE[i + 1] = (float)a[i];
    }
    if (tid == 0) g_prefE[0] = 0.0f;
    __syncthreads();

    // --- scan 2: suffix of ENsort via reversed inclusive prefix
    for (int c = 0; c < 2; c++) {
        int i = tid + 1024 * c;
        sdA[S - 1 - i] = (double)env[c];
    }
    a = sdA; b2 = sdB;
    for (int off = 1; off < S; off <<= 1) {
        __syncthreads();
        for (int c = 0; c < 2; c++) {
            int i = tid + 1024 * c;
            double v = a[i];
            if (i >= off) v += a[i - off];
            b2[i] = v;
        }
        double* t = a; a = b2; b2 = t;
    }
    __syncthreads();
    for (int c = 0; c < 2; c++) {
        int i = tid + 1024 * c;
        g_sufEN[S - 1 - i] = (float)a[i];   // sufEN[k] = sum_{m>=k} ENsort[m]
    }
    if (tid == 0) g_sufEN[S] = 0.0f;
}

// ---------------- K2: per-row constants --------------------------------------
__global__ void k2_rows(const float* __restrict__ score) {
    int id = blockIdx.x * 1024 + threadIdx.x;  // B*S = 32768 threads
    float s  = score[id];
    float es  = expf(s);
    float ens = expf(-s);
    int lo = 0, hi = S;
    while (lo < hi) {
        int mid = (lo + hi) >> 1;
        if (g_tsort[mid] <= s) lo = mid + 1; else hi = mid;
    }
    float W = ens * g_prefE[lo] + es * g_sufEN[lo];
    g_rowc[id] = make_float4(es, ens, 1.0f / W, __int_as_float(lo));
}

// ---------------- K3: fp64 warp scans of E*F (fwd) and EN*F (bwd) -----------
// blocks 0..127: forward (PrefEF); 128..255: backward (SufENF).
// block -> (batch, f-group of 8); warp w handles f = fg*8 + w.
__global__ void k3_scan(const float* __restrict__ feat) {
    int blk = blockIdx.x;
    bool fwd = blk < 128;
    int bb = (blk & 127) >> 3;
    int fg = blk & 7;
    int w = threadIdx.x >> 5, lane = threadIdx.x & 31;
    int f = fg * 8 + w;
    __shared__ float tile[32][9];   // padded: conflict-free column writes

    const float* Fb = feat + (size_t)bb * S * F;
    float* out = (fwd ? g_PrefEF : g_SufENF) + (size_t)bb * (S + 1) * F;

    if (threadIdx.x < 8)
        out[(size_t)(fwd ? 0 : S) * F + fg * 8 + threadIdx.x] = 0.0f;

    double carry = 0.0;
    int r = threadIdx.x >> 3, ci = threadIdx.x & 7;

    if (fwd) {
        for (int c = 0; c < 64; c++) {
            int m = c * 32 + lane;
            int p = g_perm[m];
            double term = (double)g_Esort[m] * (double)Fb[(size_t)p * F + f];
            #pragma unroll
            for (int d = 1; d < 32; d <<= 1) {
                double n = __shfl_up_sync(0xffffffffu, term, d);
                if (lane >= d) term += n;
            }
            double total = __shfl_sync(0xffffffffu, term, 31);
            double ov = carry + term;       // inclusive -> k = m+1 (exclusive)
            carry += total;
            tile[lane][w] = (float)ov;
            __syncthreads();
            out[(size_t)(c * 32 + 1 + r) * F + fg * 8 + ci] = tile[r][ci];
            __syncthreads();
        }
    } else {
        for (int c = 63; c >= 0; c--) {
            int m = c * 32 + lane;
            int p = g_perm[m];
            double term = (double)g_ENsort[m] * (double)Fb[(size_t)p * F + f];
            #pragma unroll
            for (int d = 1; d < 32; d <<= 1) {
                double n = __shfl_down_sync(0xffffffffu, term, d);
                if (lane + d < 32) term += n;
            }
            double total = __shfl_sync(0xffffffffu, term, 0);
            double ov = carry + term;       // inclusive suffix -> k = m
            carry += total;
            tile[lane][w] = (float)ov;
            __syncthreads();
            out[(size_t)(c * 32 + r) * F + fg * 8 + ci] = tile[r][ci];
            __syncthreads();
        }
    }
}

// ---------------- K4: fused path write + aligned lookup ----------------------
// grid (64, 16): 32 rows per CTA, 256 threads. E/EN register-cached per thread.
// path is written once and never read again -> streaming stores (__stcs) to
// keep the 268 MB stream from evicting the small hot tables out of L2.
__global__ void __launch_bounds__(256) k4_path(float* __restrict__ aligned,
                                               float* __restrict__ path) {
    int bb = blockIdx.y;
    int r0 = blockIdx.x * 32;
    int tid = threadIdx.x;
    __shared__ float4 rc[32];
    if (tid < 32) rc[tid] = g_rowc[bb * S + r0 + tid];
    __syncthreads();

    // each thread owns j = {4t..4t+3} and {1024+4t..1024+4t+3}
    const float4* EEN4 = (const float4*)g_EEN;     // float4 = 2 (E,EN) pairs
    float4 e0 = EEN4[2 * tid];
    float4 e1 = EEN4[2 * tid + 1];
    float4 e2 = EEN4[512 + 2 * tid];
    float4 e3 = EEN4[512 + 2 * tid + 1];

    float* prow = path + (size_t)(bb * S + r0) * S;
    #pragma unroll 4
    for (int r = 0; r < 32; r++) {
        float4 c = rc[r];
        float es = c.x, ens = c.y, iw = c.z;
        float4 o0, o1;
        o0.x = fminf(e0.x * ens, e0.y * es) * iw;
        o0.y = fminf(e0.z * ens, e0.w * es) * iw;
        o0.z = fminf(e1.x * ens, e1.y * es) * iw;
        o0.w = fminf(e1.z * ens, e1.w * es) * iw;
        o1.x = fminf(e2.x * ens, e2.y * es) * iw;
        o1.y = fminf(e2.z * ens, e2.w * es) * iw;
        o1.z = fminf(e3.x * ens, e3.y * es) * iw;
        o1.w = fminf(e3.z * ens, e3.w * es) * iw;
        float* pr = prow + (size_t)r * S;
        __stcs((float4*)pr + tid, o0);
        __stcs((float4*)(pr + 1024) + tid, o1);
    }

    // aligned: warp w handles rows 4w..4w+3; lane covers f and f+32
    int w = tid >> 5, lane = tid & 31;
    #pragma unroll
    for (int q = 0; q < 4; q++) {
        int rr = w * 4 + q;
        float4 c = rc[rr];
        int k = __float_as_int(c.w);
        const float* pf = g_PrefEF + ((size_t)bb * (S + 1) + k) * F;
        const float* sf = g_SufENF + ((size_t)bb * (S + 1) + k) * F;
        float* arow = aligned + (size_t)(bb * S + r0 + rr) * F;
        arow[lane]      = (c.y * pf[lane]      + c.x * sf[lane])      * c.z;
        arow[lane + 32] = (c.y * pf[lane + 32] + c.x * sf[lane + 32]) * c.z;
    }
}

// ---------------- launch ------------------------------------------------------
extern "C" void kernel_launch(void* const* d_in, const int* in_sizes, int n_in,
                              void* d_out, int out_size) {
    const float* score   = (const float*)d_in[0];  // [16,2048,1]
    const float* feature = (const float*)d_in[1];  // [16,2048,64]
    const float* tmpl    = (const float*)d_in[2];  // [1,2048,1]
    float* out = (float*)d_out;
    float* aligned = out;                      // [16,2048,64] first (tuple order)
    float* path    = out + (size_t)B * S * F;  // [16,2048,2048]

    k1_setup<<<1, 1024>>>(tmpl);
    k2_rows<<<B * S / 1024, 1024>>>(score);
    k3_scan<<<256, 256>>>(feature);
    k4_path<<<dim3(64, B), 256>>>(aligned, path);
}

// round 14
// speedup vs baseline: 1.8111x; 1.8111x over previous
#include <cuda_runtime.h>
#include <cuda_bf16.h>
#include <math.h>

// FrameAlignment: B=16, S=2048, F=64
//   dist[b,i,j] = |score[b,i] - t[j]|; path = softmax_j(-dist); aligned = path @ feature
// Separable: exp(-|s-t|) = min(e^t * e^-s, e^-t * e^s). With t sorted and
// k = #{t_j <= s}: aligned = (e^-s*PrefEF[k] + e^s*SufENF[k]) / W,
// W = e^-s*prefE[k] + e^s*sufEN[k], path[i][j] = min(E_j e^-s, EN_j e^s)/W.

#define B 16
#define S 2048
#define F 64

__device__ float  g_tsort[S];
__device__ int    g_perm[S];
__device__ float2 g_EEN[S];        // original order: (exp(t_j), exp(-t_j))
__device__ float  g_Esort[S];
__device__ float  g_ENsort[S];
__device__ float  g_prefE[S + 1];
__device__ float  g_sufEN[S + 1];
__device__ float  g_PrefEF[B * (S + 1) * F];  // 8.39 MB
__device__ float  g_SufENF[B * (S + 1) * F];  // 8.39 MB

// ---------------- K1: parallel rank sort (no barriers in compare loop) ------
// 16 blocks x 512 threads; 4 threads cooperate per element j.
__global__ void k1_sort(const float* __restrict__ tmpl) {
    __shared__ float st[S];
    int tid = threadIdx.x;
    for (int i = tid; i < S; i += 512) st[i] = tmpl[i];
    __syncthreads();

    int g   = blockIdx.x * 128 + (tid >> 2);   // element j in 0..2047
    int sub = tid & 3;
    float tj = st[g];
    int rank = 0;
    int base = sub * 512;
    #pragma unroll 8
    for (int m = base; m < base + 512; m++) {
        float tm = st[m];
        rank += (tm < tj) || (tm == tj && m < g);   // strict total order
    }
    rank += __shfl_down_sync(0xffffffffu, rank, 2);
    rank += __shfl_down_sync(0xffffffffu, rank, 1);
    if (sub == 0) {
        float e = expf(tj), en = expf(-tj);
        g_tsort[rank]  = tj;
        g_perm[rank]   = g;
        g_Esort[rank]  = e;
        g_ENsort[rank] = en;
        g_EEN[g] = make_float2(e, en);
    }
}

// ---------------- scalar fp64 scans, run as extra blocks of k3 ---------------
// which==0: exclusive prefix of Esort -> g_prefE; which==1: suffix of ENsort.
// 256 threads, 8 chunks each; Hillis-Steele with read-a/write-b/sync/swap.
__device__ void k1b_scan_block(int which) {
    __shared__ double sA[S];
    __shared__ double sB[S];
    int tid = threadIdx.x;

    if (which == 0) {
        for (int c = 0; c < 8; c++) { int i = tid + 256 * c; sA[i] = (double)g_Esort[i]; }
    } else {
        for (int c = 0; c < 8; c++) { int i = tid + 256 * c; sA[S - 1 - i] = (double)g_ENsort[i]; }
    }
    __syncthreads();
    double* a = sA; double* b = sB;
    for (int off = 1; off < S; off <<= 1) {
        for (int c = 0; c < 8; c++) {
            int i = tid + 256 * c;
            double v = a[i];
            if (i >= off) v += a[i - off];
            b[i] = v;
        }
        __syncthreads();
        double* t = a; a = b; b = t;
    }
    if (which == 0) {
        for (int c = 0; c < 8; c++) { int i = tid + 256 * c; g_prefE[i + 1] = (float)a[i]; }
        if (tid == 0) g_prefE[0] = 0.0f;
    } else {
        // a[j] = sum_{q<=j} EN[S-1-q]  ->  sufEN[S-1-j] = sum_{m>=S-1-j} EN[m]
        for (int c = 0; c < 8; c++) { int i = tid + 256 * c; g_sufEN[S - 1 - i] = (float)a[i]; }
        if (tid == 0) g_sufEN[S] = 0.0f;
    }
}

// ---------------- K3: fp32 warp scans, pipelined gather, 1 barrier/iter ------
// blocks 0..127: forward (PrefEF); 128..255: backward (SufENF);
// blocks 256..257: the scalar prefE/sufEN scans (overlap with the gathers).
// block -> (batch, f-group of 8); warp w handles f = fg*8 + w.
// Error depth = 5 (warp scan) + 64 (carry) adds: ~8e-6 rel, safe vs 1e-3.
__global__ void k3_scan(const float* __restrict__ feat) {
    int blk = blockIdx.x;
    if (blk >= 256) { k1b_scan_block(blk - 256); return; }

    bool fwd = blk < 128;
    int bb = (blk & 127) >> 3;
    int fg = blk & 7;
    int w = threadIdx.x >> 5, lane = threadIdx.x & 31;
    int f = fg * 8 + w;
    __shared__ float tile[2][32][9];   // double-buffered, padded

    const float* Fb = feat + (size_t)bb * S * F;
    float* out = (fwd ? g_PrefEF : g_SufENF) + (size_t)bb * (S + 1) * F;

    if (threadIdx.x < 8)
        out[(size_t)(fwd ? 0 : S) * F + fg * 8 + threadIdx.x] = 0.0f;

    float carry = 0.0f;
    int r = threadIdx.x >> 3, ci = threadIdx.x & 7;

    if (fwd) {
        float fpre[4];
        #pragma unroll
        for (int d = 0; d < 4; d++)
            fpre[d] = Fb[(size_t)g_perm[d * 32 + lane] * F + f];
        #pragma unroll 4
        for (int c = 0; c < 64; c++) {
            int m = c * 32 + lane;
            float term = g_Esort[m] * fpre[c & 3];
            if (c + 4 < 64)
                fpre[c & 3] = Fb[(size_t)g_perm[(c + 4) * 32 + lane] * F + f];
            #pragma unroll
            for (int d = 1; d < 32; d <<= 1) {
                float n = __shfl_up_sync(0xffffffffu, term, d);
                if (lane >= d) term += n;
            }
            float total = __shfl_sync(0xffffffffu, term, 31);
            float ov = carry + term;        // inclusive -> stored at k = m+1
            carry += total;
            tile[c & 1][lane][w] = ov;
            __syncthreads();
            out[(size_t)(c * 32 + 1 + r) * F + fg * 8 + ci] = tile[c & 1][r][ci];
        }
    } else {
        float fpre[4];
        #pragma unroll
        for (int d = 0; d < 4; d++)
            fpre[d] = Fb[(size_t)g_perm[(63 - d) * 32 + lane] * F + f];
        #pragma unroll 4
        for (int cc = 0; cc < 64; cc++) {
            int c = 63 - cc;
            int m = c * 32 + lane;
            float term = g_ENsort[m] * fpre[cc & 3];
            if (cc + 4 < 64)
                fpre[cc & 3] = Fb[(size_t)g_perm[(63 - (cc + 4)) * 32 + lane] * F + f];
            #pragma unroll
            for (int d = 1; d < 32; d <<= 1) {
                float n = __shfl_down_sync(0xffffffffu, term, d);
                if (lane + d < 32) term += n;
            }
            float total = __shfl_sync(0xffffffffu, term, 0);
            float ov = carry + term;        // inclusive suffix -> k = m
            carry += total;
            tile[cc & 1][lane][w] = ov;
            __syncthreads();
            out[(size_t)(c * 32 + r) * F + fg * 8 + ci] = tile[cc & 1][r][ci];
        }
    }
}

// ---------------- K4: row constants + path write + aligned lookup ------------
// grid (64, 16): 32 rows per CTA, 256 threads. Store body unchanged from the
// measured 50us/57%-DRAM version; row-constant computation folded in.
__global__ void __launch_bounds__(256) k4_path(const float* __restrict__ score,
                                               float* __restrict__ aligned,
                                               float* __restrict__ path) {
    int bb = blockIdx.y;
    int r0 = blockIdx.x * 32;
    int tid = threadIdx.x;
    __shared__ float4 rc[32];
    if (tid < 32) {
        float s = score[bb * S + r0 + tid];
        float es = expf(s), ens = expf(-s);
        int lo = 0, hi = S;
        while (lo < hi) {
            int mid = (lo + hi) >> 1;
            if (g_tsort[mid] <= s) lo = mid + 1; else hi = mid;
        }
        float W = ens * g_prefE[lo] + es * g_sufEN[lo];
        rc[tid] = make_float4(es, ens, 1.0f / W, __int_as_float(lo));
    }
    __syncthreads();

    const float4* EEN4 = (const float4*)g_EEN;     // float4 = 2 (E,EN) pairs
    float4 e0 = EEN4[2 * tid];
    float4 e1 = EEN4[2 * tid + 1];
    float4 e2 = EEN4[512 + 2 * tid];
    float4 e3 = EEN4[512 + 2 * tid + 1];

    float* prow = path + (size_t)(bb * S + r0) * S;
    #pragma unroll 4
    for (int r = 0; r < 32; r++) {
        float4 c = rc[r];
        float es = c.x, ens = c.y, iw = c.z;
        float4 o0, o1;
        o0.x = fminf(e0.x * ens, e0.y * es) * iw;
        o0.y = fminf(e0.z * ens, e0.w * es) * iw;
        o0.z = fminf(e1.x * ens, e1.y * es) * iw;
        o0.w = fminf(e1.z * ens, e1.w * es) * iw;
        o1.x = fminf(e2.x * ens, e2.y * es) * iw;
        o1.y = fminf(e2.z * ens, e2.w * es) * iw;
        o1.z = fminf(e3.x * ens, e3.y * es) * iw;
        o1.w = fminf(e3.z * ens, e3.w * es) * iw;
        float* pr = prow + (size_t)r * S;
        __stcs((float4*)pr + tid, o0);
        __stcs((float4*)(pr + 1024) + tid, o1);
    }

    int w = tid >> 5, lane = tid & 31;
    #pragma unroll
    for (int q = 0; q < 4; q++) {
        int rr = w * 4 + q;
        float4 c = rc[rr];
        int k = __float_as_int(c.w);
        const float* pf = g_PrefEF + ((size_t)bb * (S + 1) + k) * F;
        const float* sf = g_SufENF + ((size_t)bb * (S + 1) + k) * F;
        float* arow = aligned + (size_t)(bb * S + r0 + rr) * F;
        arow[lane]      = (c.y * pf[lane]      + c.x * sf[lane])      * c.z;
        arow[lane + 32] = (c.y * pf[lane + 32] + c.x * sf[lane + 32]) * c.z;
    }
}

// ---------------- launch ------------------------------------------------------
extern "C" void kernel_launch(void* const* d_in, const int* in_sizes, int n_in,
                              void* d_out, int out_size) {
    const float* score   = (const float*)d_in[0];  // [16,2048,1]
    const float* feature = (const float*)d_in[1];  // [16,2048,64]
    const float* tmpl    = (const float*)d_in[2];  // [1,2048,1]
    float* out = (float*)d_out;
    float* aligned = out;                      // [16,2048,64] first (tuple order)
    float* path    = out + (size_t)B * S * F;  // [16,2048,2048]

    k1_sort<<<16, 512>>>(tmpl);
    k3_scan<<<258, 256>>>(feature);            // blocks 256..257 = scalar scans
    k4_path<<<dim3(64, B), 256>>>(score, aligned, path);
}

// round 17
// speedup vs baseline: 2.0601x; 1.1375x over previous
#include <cuda_runtime.h>
#include <cuda_bf16.h>
#include <math.h>

// FrameAlignment: B=16, S=2048, F=64
//   dist[b,i,j] = |score[b,i] - t[j]|; path = softmax_j(-dist); aligned = path @ feature
// Separable: exp(-|s-t|) = min(e^t * e^-s, e^-t * e^s). With t sorted and
// k = #{t_j <= s}: aligned = (e^-s*PrefEF[k] + e^s*SufENF[k]) / W,
// W = e^-s*prefE[k] + e^s*sufEN[k], path[i][j] = min(E_j e^-s, EN_j e^s)/W.

#define B 16
#define S 2048
#define F 64

__device__ float  g_tsort[S];
__device__ int    g_perm[S];
__device__ float2 g_EEN[S];        // original order: (exp(t_j), exp(-t_j))
__device__ float  g_Esort[S];
__device__ float  g_ENsort[S];
__device__ float  g_prefE[S + 1];
__device__ float  g_sufEN[S + 1];
__device__ float  g_PrefEF[B * (S + 1) * F];  // 8.39 MB
__device__ float  g_SufENF[B * (S + 1) * F];  // 8.39 MB

// ---------------- K1: rank sort, one warp per element ------------------------
// 256 blocks x 256 threads. Warp w of block b owns element g = b*8+w; each
// lane compares 64 candidates (conflict-free m = i*32+lane), 5-shfl reduce.
// Was 16x512 with 512 compares/thread: issue-bound on 16 SMs at 22us.
__global__ void k1_sort(const float* __restrict__ tmpl) {
    __shared__ float st[S];
    int tid = threadIdx.x;
    for (int i = tid; i < S; i += 256) st[i] = tmpl[i];
    __syncthreads();

    int warp = tid >> 5, lane = tid & 31;
    int g = blockIdx.x * 8 + warp;             // element 0..2047
    float tj = st[g];
    int rank = 0;
    #pragma unroll 8
    for (int i = 0; i < 64; i++) {
        int m = i * 32 + lane;
        float tm = st[m];
        rank += (tm < tj) || (tm == tj && m < g);   // strict total order
    }
    #pragma unroll
    for (int d = 16; d > 0; d >>= 1)
        rank += __shfl_down_sync(0xffffffffu, rank, d);
    if (lane == 0) {
        float e = expf(tj), en = expf(-tj);
        g_tsort[rank]  = tj;
        g_perm[rank]   = g;
        g_Esort[rank]  = e;
        g_ENsort[rank] = en;
        g_EEN[g] = make_float2(e, en);
    }
}

// ---------------- scalar fp64 scans, run as extra blocks of k3 ---------------
// which==0: exclusive prefix of Esort -> g_prefE; which==1: suffix of ENsort.
// 256 threads, 8 chunks each; Hillis-Steele with read-a/write-b/sync/swap.
__device__ void k1b_scan_block(int which) {
    __shared__ double sA[S];
    __shared__ double sB[S];
    int tid = threadIdx.x;

    if (which == 0) {
        for (int c = 0; c < 8; c++) { int i = tid + 256 * c; sA[i] = (double)g_Esort[i]; }
    } else {
        for (int c = 0; c < 8; c++) { int i = tid + 256 * c; sA[S - 1 - i] = (double)g_ENsort[i]; }
    }
    __syncthreads();
    double* a = sA; double* b = sB;
    for (int off = 1; off < S; off <<= 1) {
        for (int c = 0; c < 8; c++) {
            int i = tid + 256 * c;
            double v = a[i];
            if (i >= off) v += a[i - off];
            b[i] = v;
        }
        __syncthreads();
        double* t = a; a = b; b = t;
    }
    if (which == 0) {
        for (int c = 0; c < 8; c++) { int i = tid + 256 * c; g_prefE[i + 1] = (float)a[i]; }
        if (tid == 0) g_prefE[0] = 0.0f;
    } else {
        // a[j] = sum_{q<=j} EN[S-1-q]  ->  sufEN[S-1-j] = sum_{m>=S-1-j} EN[m]
        for (int c = 0; c < 8; c++) { int i = tid + 256 * c; g_sufEN[S - 1 - i] = (float)a[i]; }
        if (tid == 0) g_sufEN[S] = 0.0f;
    }
}

// ---------------- K3: fp32 warp scans, pipelined gather, 1 barrier/iter ------
// blocks 0..127: forward (PrefEF); 128..255: backward (SufENF);
// blocks 256..257: the scalar prefE/sufEN scans (overlap with the gathers).
// block -> (batch, f-group of 8); warp w handles f = fg*8 + w.
// Error depth = 5 (warp scan) + 64 (carry) adds: ~8e-6 rel, safe vs 1e-3.
__global__ void k3_scan(const float* __restrict__ feat) {
    int blk = blockIdx.x;
    if (blk >= 256) { k1b_scan_block(blk - 256); return; }

    bool fwd = blk < 128;
    int bb = (blk & 127) >> 3;
    int fg = blk & 7;
    int w = threadIdx.x >> 5, lane = threadIdx.x & 31;
    int f = fg * 8 + w;
    __shared__ float tile[2][32][9];   // double-buffered, padded

    const float* Fb = feat + (size_t)bb * S * F;
    float* out = (fwd ? g_PrefEF : g_SufENF) + (size_t)bb * (S + 1) * F;

    if (threadIdx.x < 8)
        out[(size_t)(fwd ? 0 : S) * F + fg * 8 + threadIdx.x] = 0.0f;

    float carry = 0.0f;
    int r = threadIdx.x >> 3, ci = threadIdx.x & 7;

    if (fwd) {
        float fpre[4];
        #pragma unroll
        for (int d = 0; d < 4; d++)
            fpre[d] = Fb[(size_t)g_perm[d * 32 + lane] * F + f];
        #pragma unroll 4
        for (int c = 0; c < 64; c++) {
            int m = c * 32 + lane;
            float term = g_Esort[m] * fpre[c & 3];
            if (c + 4 < 64)
                fpre[c & 3] = Fb[(size_t)g_perm[(c + 4) * 32 + lane] * F + f];
            #pragma unroll
            for (int d = 1; d < 32; d <<= 1) {
                float n = __shfl_up_sync(0xffffffffu, term, d);
                if (lane >= d) term += n;
            }
            float total = __shfl_sync(0xffffffffu, term, 31);
            float ov = carry + term;        // inclusive -> stored at k = m+1
            carry += total;
            tile[c & 1][lane][w] = ov;
            __syncthreads();
            out[(size_t)(c * 32 + 1 + r) * F + fg * 8 + ci] = tile[c & 1][r][ci];
        }
    } else {
        float fpre[4];
        #pragma unroll
        for (int d = 0; d < 4; d++)
            fpre[d] = Fb[(size_t)g_perm[(63 - d) * 32 + lane] * F + f];
        #pragma unroll 4
        for (int cc = 0; cc < 64; cc++) {
            int c = 63 - cc;
            int m = c * 32 + lane;
            float term = g_ENsort[m] * fpre[cc & 3];
            if (cc + 4 < 64)
                fpre[cc & 3] = Fb[(size_t)g_perm[(63 - (cc + 4)) * 32 + lane] * F + f];
            #pragma unroll
            for (int d = 1; d < 32; d <<= 1) {
                float n = __shfl_down_sync(0xffffffffu, term, d);
                if (lane + d < 32) term += n;
            }
            float total = __shfl_sync(0xffffffffu, term, 0);
            float ov = carry + term;        // inclusive suffix -> k = m
            carry += total;
            tile[cc & 1][lane][w] = ov;
            __syncthreads();
            out[(size_t)(c * 32 + r) * F + fg * 8 + ci] = tile[cc & 1][r][ci];
        }
    }
}

// ---------------- K4: row constants + path write + aligned lookup ------------
// grid (64, 16): 32 rows per CTA, 256 threads. Store body unchanged from the
// measured 50us/57%-DRAM version; row-constant computation folded in.
__global__ void __launch_bounds__(256) k4_path(const float* __restrict__ score,
                                               float* __restrict__ aligned,
                                               float* __restrict__ path) {
    int bb = blockIdx.y;
    int r0 = blockIdx.x * 32;
    int tid = threadIdx.x;
    __shared__ float4 rc[32];
    if (tid < 32) {
        float s = score[bb * S + r0 + tid];
        float es = expf(s), ens = expf(-s);
        int lo = 0, hi = S;
        while (lo < hi) {
            int mid = (lo + hi) >> 1;
            if (g_tsort[mid] <= s) lo = mid + 1; else hi = mid;
        }
        float W = ens * g_prefE[lo] + es * g_sufEN[lo];
        rc[tid] = make_float4(es, ens, 1.0f / W, __int_as_float(lo));
    }
    __syncthreads();

    const float4* EEN4 = (const float4*)g_EEN;     // float4 = 2 (E,EN) pairs
    float4 e0 = EEN4[2 * tid];
    float4 e1 = EEN4[2 * tid + 1];
    float4 e2 = EEN4[512 + 2 * tid];
    float4 e3 = EEN4[512 + 2 * tid + 1];

    float* prow = path + (size_t)(bb * S + r0) * S;
    #pragma unroll 4
    for (int r = 0; r < 32; r++) {
        float4 c = rc[r];
        float es = c.x, ens = c.y, iw = c.z;
        float4 o0, o1;
        o0.x = fminf(e0.x * ens, e0.y * es) * iw;
        o0.y = fminf(e0.z * ens, e0.w * es) * iw;
        o0.z = fminf(e1.x * ens, e1.y * es) * iw;
        o0.w = fminf(e1.z * ens, e1.w * es) * iw;
        o1.x = fminf(e2.x * ens, e2.y * es) * iw;
        o1.y = fminf(e2.z * ens, e2.w * es) * iw;
        o1.z = fminf(e3.x * ens, e3.y * es) * iw;
        o1.w = fminf(e3.z * ens, e3.w * es) * iw;
        float* pr = prow + (size_t)r * S;
        __stcs((float4*)pr + tid, o0);
        __stcs((float4*)(pr + 1024) + tid, o1);
    }

    int w = tid >> 5, lane = tid & 31;
    #pragma unroll
    for (int q = 0; q < 4; q++) {
        int rr = w * 4 + q;
        float4 c = rc[rr];
        int k = __float_as_int(c.w);
        const float* pf = g_PrefEF + ((size_t)bb * (S + 1) + k) * F;
        const float* sf = g_SufENF + ((size_t)bb * (S + 1) + k) * F;
        float* arow = aligned + (size_t)(bb * S + r0 + rr) * F;
        arow[lane]      = (c.y * pf[lane]      + c.x * sf[lane])      * c.z;
        arow[lane + 32] = (c.y * pf[lane + 32] + c.x * sf[lane + 32]) * c.z;
    }
}

// ---------------- launch ------------------------------------------------------
extern "C" void kernel_launch(void* const* d_in, const int* in_sizes, int n_in,
                              void* d_out, int out_size) {
    const float* score   = (const float*)d_in[0];  // [16,2048,1]
    const float* feature = (const float*)d_in[1];  // [16,2048,64]
    const float* tmpl    = (const float*)d_in[2];  // [1,2048,1]
    float* out = (float*)d_out;
    float* aligned = out;                      // [16,2048,64] first (tuple order)
    float* path    = out + (size_t)B * S * F;  // [16,2048,2048]

    k1_sort<<<256, 256>>>(tmpl);
    k3_scan<<<258, 256>>>(feature);            // blocks 256..257 = scalar scans
    k4_path<<<dim3(64, B), 256>>>(score, aligned, path);
}